// round 14
// baseline (speedup 1.0000x reference)
#include <cuda_runtime.h>
#include <math.h>
#include <stdint.h>

// AttnPooling B=8,N=16 -> BN=128; D=128; K=4096.
// l_k = q.(Wk x_k + bk) = (Wk^T q).x_k + const (cancels in softmax).
// SINGLE fused kernel, 512 blocks = 128 bn-quads x 4 chunks, all resident
// (occ 4). Per block: pass A masked-sum over its 1024-k chunk -> quad atomic
// barrier -> redundant q2 compute -> pass B online-softmax pooling (3-stage
// cp.async ring + L2 prefetch 5 tiles ahead, 2 barriers/tile) -> last block
// of each quad combines.

#define BN  128
#define DD  128
#define KK  4096
#define NCH 4
#define CK  (KK / NCH)       // 1024 k per chunk
#define TT  32               // k-tile in pass B
#define NTC (CK / TT)        // 32 tiles
#define NTH 256
#define TILE_BYTES (DD * TT * 4)   // 16384

// scratch (__device__ globals: no allocation)
__device__ float g_sum[BN * NCH * DD];
__device__ float g_cnt[BN * NCH];
__device__ float g_pp[BN * NCH * DD];
__device__ float g_pm[BN * NCH];
__device__ float g_ps[BN * NCH];
__device__ unsigned int g_sync[2 * BN];   // [0..BN) pass-A arrivals, [BN..2BN) pass-B

// smem float offsets
#define OFF_BUF  0
#define OFF_MSK  (3 * DD * TT)        // 12288 ; pass-A mask (CK floats)
#define OFF_PART (OFF_MSK + CK)       // 13312 ; logit partials / mean+q (256)
#define OFF_Q2   (OFF_PART + 256)     // 13568
#define OFF_RED  (OFF_Q2 + DD)        // 13696
#define OFF_SCAL (OFF_RED + 32)       // 13728
#define SMF      (OFF_SCAL + 4)       // 13732 floats = 54928 B -> occ 4

__device__ __forceinline__ float warp_sum(float v) {
#pragma unroll
    for (int o = 16; o > 0; o >>= 1) v += __shfl_xor_sync(0xffffffffu, v, o);
    return v;
}
__device__ __forceinline__ float warp_max(float v) {
#pragma unroll
    for (int o = 16; o > 0; o >>= 1) v = fmaxf(v, __shfl_xor_sync(0xffffffffu, v, o));
    return v;
}
__device__ __forceinline__ uint32_t smem_u32(const void* p) {
    uint32_t a;
    asm("{ .reg .u64 t; cvta.to.shared.u64 t, %1; cvt.u32.u64 %0, t; }" : "=r"(a) : "l"(p));
    return a;
}
__device__ __forceinline__ void cp_async16(uint32_t dst, const void* src) {
    asm volatile("cp.async.cg.shared.global [%0], [%1], 16;" :: "r"(dst), "l"(src) : "memory");
}
__device__ __forceinline__ void cp_commit() {
    asm volatile("cp.async.commit_group;" ::: "memory");
}
__device__ __forceinline__ void cp_wait0() {
    asm volatile("cp.async.wait_group 0;" ::: "memory");
}
__device__ __forceinline__ void cp_wait1() {
    asm volatile("cp.async.wait_group 1;" ::: "memory");
}
__device__ __forceinline__ void pf_l2(const void* p) {
    asm volatile("prefetch.global.L2 [%0];" :: "l"(p));
}

// one tile = 128 rows x 32 floats = 1024 float4; 256 thr x 4 copies
__device__ __forceinline__ void issue_tile(uint32_t base, const float* __restrict__ xb,
                                           int rt, int tid) {
#pragma unroll
    for (int j = 0; j < 4; j++) {
        const int idx = tid + NTH * j;
        const int row = idx >> 3;
        const int c4  = idx & 7;
        cp_async16(base + (uint32_t)row * (TT * 4) + (uint32_t)c4 * 16,
                   xb + (size_t)row * KK + rt * TT + c4 * 4);
    }
}

__global__ void __launch_bounds__(NTH, 4)
fused_attn_pool(const float* __restrict__ x, const int* __restrict__ mask,
                const float* __restrict__ Wq, const float* __restrict__ bq,
                const float* __restrict__ Wk, float* __restrict__ out)
{
    extern __shared__ float sm[];
    float* buf  = sm + OFF_BUF;
    float* msk  = sm + OFF_MSK;       // mask as float, CK entries
    float* part = sm + OFF_PART;      // logit partials; also mean(0..127)+q(128..255)
    float* q2s  = sm + OFF_Q2;
    float* reds = sm + OFF_RED;
    float* scal = sm + OFF_SCAL;

    const int tid  = threadIdx.x;
    const int lane = tid & 31;
    const int aw   = tid >> 5;        // 8 warps
    const int bn   = blockIdx.x >> 2;
    const int c    = blockIdx.x & 3;
    const float NEG_INF = __int_as_float(0xff800000);

    const float* xb = x + (size_t)bn * (DD * KK) + (size_t)c * CK;
    const int*   mb = mask + (size_t)bn * KK + (size_t)c * CK;
    const uint32_t bufb = smem_u32(buf);

    // ================= pass A: mask + masked partial sums =================
    float cnt = 0.f;
    for (int i = tid; i < CK; i += NTH) {
        const float v = (float)mb[i];
        msk[i] = v;
        cnt += v;
    }
    cnt = warp_sum(cnt);
    if (lane == 0) reds[aw] = cnt;
    __syncthreads();
    if (tid == 0) {
        float s = 0.f;
#pragma unroll
        for (int w = 0; w < 8; w++) s += reds[w];
        g_cnt[bn * NCH + c] = s;
    }

    const float4* m4 = (const float4*)msk;
#pragma unroll 2
    for (int i = 0; i < 16; i++) {
        const int d = aw * 16 + i;
        const float* row = xb + (size_t)d * KK;
        if (i < 14) pf_l2(row + 2 * KK + lane * 32);   // 2 rows ahead -> L2
        float s = 0.f;
#pragma unroll
        for (int j = 0; j < 8; j++) {
            const float4 v = *(const float4*)(row + j * 128 + lane * 4);
            const float4 m = m4[j * 32 + lane];
            s = fmaf(v.x, m.x, s);
            s = fmaf(v.y, m.y, s);
            s = fmaf(v.z, m.z, s);
            s = fmaf(v.w, m.w, s);
        }
        s = warp_sum(s);
        if (lane == 0) g_sum[(bn * NCH + c) * DD + d] = s;
    }
    __syncthreads();   // all g_sum/g_cnt stores issued

    // prefetch first two pass-B tiles (reverse order) + L2-prime tiles 2..4
    issue_tile(bufb,              xb, NTC - 1, tid); cp_commit();
    issue_tile(bufb + TILE_BYTES, xb, NTC - 2, tid); cp_commit();
    if (tid < DD) {
#pragma unroll
        for (int i = 2; i <= 4; i++)
            pf_l2(xb + (size_t)tid * KK + (NTC - 1 - i) * TT);
    }

    // ============== quad barrier (4 chunk-blocks of this bn) ==============
    if (tid == 0) {
        __threadfence();
        atomicAdd(&g_sync[bn], 1u);
        while (((volatile unsigned int*)g_sync)[bn] < (unsigned)NCH) __nanosleep(64);
        __threadfence();
    }
    __syncthreads();

    // ============== redundant q2 compute (per block) ==============
    float* mean_s = part;            // [0..127]
    float* q_s    = part + 128;      // [128..255]
    if (tid < DD) {
        float cs = 0.f, ss = 0.f;
#pragma unroll
        for (int c2 = 0; c2 < NCH; c2++) {
            cs += g_cnt[bn * NCH + c2];
            ss += g_sum[(bn * NCH + c2) * DD + tid];
        }
        mean_s[tid] = ss / cs;
    }
    __syncthreads();
#pragma unroll 2
    for (int ii = 0; ii < 16; ii++) {
        const int r = aw * 16 + ii;
        float s = 0.f;
#pragma unroll
        for (int b = 0; b < 4; b++) {
            const int j = lane + 32 * b;
            s = fmaf(Wq[r * DD + j], mean_s[j], s);
        }
        s = warp_sum(s);
        if (lane == 0) q_s[r] = s + bq[r];
    }
    __syncthreads();
    float q2v = 0.f;
    if (tid < DD) {
#pragma unroll 8
        for (int j = 0; j < DD; j++)
            q2v = fmaf(Wk[j * DD + tid], q_s[j], q2v);
    }
    // per-lane mask bits: bit t = mask of k=(t*TT+lane) in this chunk
    uint32_t mbits = 0;
#pragma unroll
    for (int t = 0; t < NTC; t++)
        mbits |= (msk[t * TT + lane] != 0.f ? 1u : 0u) << t;
    __syncthreads();   // mean/q dead
    if (tid < DD) q2s[tid] = q2v * 0.08838834764831845f;   // 1/sqrt(128)
    __syncthreads();   // q2s visible

    // ======== pass B: online softmax, reverse tiles, 2 barriers/tile ========
    float Mrun = NEG_INF;
    float den  = 0.f;
    float pd[16];
#pragma unroll
    for (int i = 0; i < 16; i++) pd[i] = 0.f;

    for (int i = 0; i < NTC; i++) {
        const int rt = NTC - 1 - i;        // actual tile (reverse)
        const int st = i % 3;
        if (i == NTC - 1) cp_wait0(); else cp_wait1();
        __syncthreads();   // S0: tile i ready; stage (i%3) from i-3 consumed

        if (i + 2 < NTC) {
            issue_tile(bufb + (uint32_t)((i + 2) % 3) * TILE_BYTES,
                       xb, NTC - 1 - (i + 2), tid);
            cp_commit();
        }
        if (i + 5 < NTC && tid < DD)   // DRAM -> L2, 5 tiles ahead
            pf_l2(xb + (size_t)tid * KK + (NTC - 1 - (i + 5)) * TT);

        const float* B = buf + st * (DD * TT);
        // phase L: warp aw covers d = aw*16..+15, k = lane
        {
            float acc = 0.f;
#pragma unroll
            for (int j = 0; j < 16; j++) {
                const int d = aw * 16 + j;
                acc = fmaf(q2s[d], B[d * TT + lane], acc);
            }
            part[aw * TT + lane] = acc;
        }
        __syncthreads();   // B1

        // every warp redundantly: combine partials, mask, max, alpha, weights
        float l = 0.f;
#pragma unroll
        for (int g = 0; g < 8; g++) l += part[g * TT + lane];
        l = ((mbits >> rt) & 1u) ? l : NEG_INF;
        const float tm = warp_max(l);
        const float nM = fmaxf(Mrun, tm);
        const float alpha = (nM == NEG_INF) ? 0.f : __expf(Mrun - nM);
        const float w     = (nM == NEG_INF) ? 0.f : __expf(l - nM);
        Mrun = nM;
        den = fmaf(den, alpha, warp_sum(w));

#pragma unroll
        for (int ii = 0; ii < 16; ii++) {
            const int d = aw * 16 + ii;
            pd[ii] = fmaf(pd[ii], alpha, w * B[d * TT + lane]);
        }
        // next iteration's S0 protects part + stage reuse
    }

    // ================= epilogue: partials + last-block combine =================
#pragma unroll
    for (int ii = 0; ii < 16; ii++) {
        const float s = warp_sum(pd[ii]);
        if (lane == 0) g_pp[(bn * NCH + c) * DD + aw * 16 + ii] = s;
    }
    if (tid == 0) {
        g_ps[bn * NCH + c] = den;    // warp-uniform, identical in all warps
        g_pm[bn * NCH + c] = Mrun;
        __threadfence();
        const unsigned old = atomicAdd(&g_sync[BN + bn], 1u);
        ((unsigned*)scal)[0] = old;
    }
    __syncthreads();

    if (((const unsigned*)scal)[0] == (unsigned)(NCH - 1)) {
        __threadfence();   // acquire: partials from sibling blocks
        if (tid < DD) {
            float pm[NCH];
            float M = NEG_INF;
#pragma unroll
            for (int c2 = 0; c2 < NCH; c2++) {
                pm[c2] = g_pm[bn * NCH + c2];
                M = fmaxf(M, pm[c2]);
            }
            float num = 0.f, dsum = 0.f;
#pragma unroll
            for (int c2 = 0; c2 < NCH; c2++) {
                const float e = __expf(pm[c2] - M);   // exp(-inf - finite) = 0
                num  = fmaf(e, g_pp[(bn * NCH + c2) * DD + tid], num);
                dsum = fmaf(e, g_ps[bn * NCH + c2], dsum);
            }
            out[bn * DD + tid] = num / dsum;
        }
    }
}

extern "C" void kernel_launch(void* const* d_in, const int* in_sizes, int n_in,
                              void* d_out, int out_size) {
    const float* x    = (const float*)d_in[0];
    const int*   mask = (const int*)d_in[1];
    const float* Wq   = (const float*)d_in[2];
    const float* bq   = (const float*)d_in[3];
    const float* Wk   = (const float*)d_in[4];
    const float* bk   = (const float*)d_in[5];
    float* out = (float*)d_out;
    (void)bk; (void)in_sizes; (void)n_in; (void)out_size;  // bk cancels in softmax

    void* sp = nullptr;
    cudaGetSymbolAddress(&sp, g_sync);
    cudaMemsetAsync(sp, 0, 2 * BN * sizeof(unsigned int));

    const size_t smem = (size_t)SMF * sizeof(float);
    cudaFuncSetAttribute(fused_attn_pool,
                         cudaFuncAttributeMaxDynamicSharedMemorySize, (int)smem);
    fused_attn_pool<<<BN * NCH, NTH, smem>>>(x, mask, Wq, bq, Wk, out);
}

// round 16
// speedup vs baseline: 1.3594x; 1.3594x over previous
#include <cuda_runtime.h>
#include <math.h>
#include <stdint.h>

// AttnPooling B=8,N=16 -> BN=128; D=128; K=4096.
// l_k = q.(Wk x_k + bk) = (Wk^T q).x_k + const (cancels in softmax).
// SINGLE fused kernel, 512 blocks = 128 bn-quads x 4 chunks, all resident
// (occ 4). Per block: pass A masked-sum over its 1024-k chunk -> quad atomic
// barrier -> redundant q2 compute -> pass B online-softmax pooling (3-stage
// cp.async ring, 2 barriers/tile, per-lane distributed denominator) -> last
// block of each quad combines.

#define BN  128
#define DD  128
#define KK  4096
#define NCH 4
#define CK  (KK / NCH)       // 1024 k per chunk
#define TT  32               // k-tile in pass B
#define NTC (CK / TT)        // 32 tiles
#define NTH 256
#define TILE_BYTES (DD * TT * 4)   // 16384

// scratch (__device__ globals: no allocation)
__device__ float g_sum[BN * NCH * DD];
__device__ float g_cnt[BN * NCH];
__device__ float g_pp[BN * NCH * DD];
__device__ float g_pm[BN * NCH];
__device__ float g_ps[BN * NCH];
__device__ unsigned int g_sync[2 * BN];   // [0..BN) pass-A arrivals, [BN..2BN) pass-B

// smem float offsets
#define OFF_BUF  0
#define OFF_MSK  (3 * DD * TT)        // 12288 ; pass-A mask (CK floats)
#define OFF_PART (OFF_MSK + CK)       // 13312 ; logit partials / mean+q (256)
#define OFF_Q2   (OFF_PART + 256)     // 13568
#define OFF_RED  (OFF_Q2 + DD)        // 13696
#define OFF_SCAL (OFF_RED + 32)       // 13728
#define SMF      (OFF_SCAL + 4)       // 13732 floats = 54928 B -> occ 4

__device__ __forceinline__ float warp_sum(float v) {
#pragma unroll
    for (int o = 16; o > 0; o >>= 1) v += __shfl_xor_sync(0xffffffffu, v, o);
    return v;
}
__device__ __forceinline__ float warp_max(float v) {
#pragma unroll
    for (int o = 16; o > 0; o >>= 1) v = fmaxf(v, __shfl_xor_sync(0xffffffffu, v, o));
    return v;
}
__device__ __forceinline__ uint32_t smem_u32(const void* p) {
    uint32_t a;
    asm("{ .reg .u64 t; cvta.to.shared.u64 t, %1; cvt.u32.u64 %0, t; }" : "=r"(a) : "l"(p));
    return a;
}
__device__ __forceinline__ void cp_async16(uint32_t dst, const void* src) {
    asm volatile("cp.async.cg.shared.global [%0], [%1], 16;" :: "r"(dst), "l"(src) : "memory");
}
__device__ __forceinline__ void cp_commit() {
    asm volatile("cp.async.commit_group;" ::: "memory");
}
__device__ __forceinline__ void cp_wait0() {
    asm volatile("cp.async.wait_group 0;" ::: "memory");
}
__device__ __forceinline__ void cp_wait1() {
    asm volatile("cp.async.wait_group 1;" ::: "memory");
}

// one tile = 128 rows x 32 floats = 1024 float4; 256 thr x 4 copies
__device__ __forceinline__ void issue_tile(uint32_t base, const float* __restrict__ xb,
                                           int rt, int tid) {
#pragma unroll
    for (int j = 0; j < 4; j++) {
        const int idx = tid + NTH * j;
        const int row = idx >> 3;
        const int c4  = idx & 7;
        cp_async16(base + (uint32_t)row * (TT * 4) + (uint32_t)c4 * 16,
                   xb + (size_t)row * KK + rt * TT + c4 * 4);
    }
}

__global__ void __launch_bounds__(NTH, 4)
fused_attn_pool(const float* __restrict__ x, const int* __restrict__ mask,
                const float* __restrict__ Wq, const float* __restrict__ bq,
                const float* __restrict__ Wk, float* __restrict__ out)
{
    extern __shared__ float sm[];
    float* buf  = sm + OFF_BUF;
    float* msk  = sm + OFF_MSK;       // mask as float, CK entries
    float* part = sm + OFF_PART;      // logit partials; also mean(0..127)+q(128..255)
    float* q2s  = sm + OFF_Q2;
    float* reds = sm + OFF_RED;
    float* scal = sm + OFF_SCAL;

    const int tid  = threadIdx.x;
    const int lane = tid & 31;
    const int aw   = tid >> 5;        // 8 warps
    const int bn   = blockIdx.x >> 2;
    const int c    = blockIdx.x & 3;
    const float NEG_INF = __int_as_float(0xff800000);

    const float* xb = x + (size_t)bn * (DD * KK) + (size_t)c * CK;
    const int*   mb = mask + (size_t)bn * KK + (size_t)c * CK;
    const uint32_t bufb = smem_u32(buf);

    // ================= pass A: mask + masked partial sums =================
    float cnt = 0.f;
    for (int i = tid; i < CK; i += NTH) {
        const float v = (float)mb[i];
        msk[i] = v;
        cnt += v;
    }
    cnt = warp_sum(cnt);
    if (lane == 0) reds[aw] = cnt;
    __syncthreads();
    if (tid == 0) {
        float s = 0.f;
#pragma unroll
        for (int w = 0; w < 8; w++) s += reds[w];
        g_cnt[bn * NCH + c] = s;
    }

    const float4* m4 = (const float4*)msk;
#pragma unroll 2
    for (int i = 0; i < 16; i++) {
        const int d = aw * 16 + i;
        const float* row = xb + (size_t)d * KK;
        float s = 0.f;
#pragma unroll
        for (int j = 0; j < 8; j++) {
            const float4 v = *(const float4*)(row + j * 128 + lane * 4);
            const float4 m = m4[j * 32 + lane];
            s = fmaf(v.x, m.x, s);
            s = fmaf(v.y, m.y, s);
            s = fmaf(v.z, m.z, s);
            s = fmaf(v.w, m.w, s);
        }
        s = warp_sum(s);
        if (lane == 0) g_sum[(bn * NCH + c) * DD + d] = s;
    }
    __syncthreads();   // all g_sum/g_cnt stores issued

    // prefetch first two pass-B tiles (overlaps quad sync + q2 compute)
    issue_tile(bufb,              xb, 0, tid); cp_commit();
    issue_tile(bufb + TILE_BYTES, xb, 1, tid); cp_commit();

    // ============== quad barrier (4 chunk-blocks of this bn) ==============
    if (tid == 0) {
        __threadfence();
        atomicAdd(&g_sync[bn], 1u);
        while (((volatile unsigned int*)g_sync)[bn] < (unsigned)NCH) __nanosleep(64);
        __threadfence();
    }
    __syncthreads();

    // ============== redundant q2 compute (per block) ==============
    float* mean_s = part;            // [0..127]
    float* q_s    = part + 128;      // [128..255]
    if (tid < DD) {
        float cs = 0.f, ss = 0.f;
#pragma unroll
        for (int c2 = 0; c2 < NCH; c2++) {
            cs += g_cnt[bn * NCH + c2];
            ss += g_sum[(bn * NCH + c2) * DD + tid];
        }
        mean_s[tid] = ss / cs;
    }
    __syncthreads();
#pragma unroll 2
    for (int ii = 0; ii < 16; ii++) {
        const int r = aw * 16 + ii;
        float s = 0.f;
#pragma unroll
        for (int b = 0; b < 4; b++) {
            const int j = lane + 32 * b;
            s = fmaf(Wq[r * DD + j], mean_s[j], s);
        }
        s = warp_sum(s);
        if (lane == 0) q_s[r] = s + bq[r];
    }
    __syncthreads();
    float q2v = 0.f;
    if (tid < DD) {
#pragma unroll 8
        for (int j = 0; j < DD; j++)
            q2v = fmaf(Wk[j * DD + tid], q_s[j], q2v);
    }
    // per-lane mask bits: bit t = mask of k=(t*TT+lane) in this chunk
    uint32_t mbits = 0;
#pragma unroll
    for (int t = 0; t < NTC; t++)
        mbits |= (msk[t * TT + lane] != 0.f ? 1u : 0u) << t;
    __syncthreads();   // mean/q dead
    if (tid < DD) q2s[tid] = q2v * 0.08838834764831845f;   // 1/sqrt(128)
    __syncthreads();   // q2s visible

    // ======== pass B: online softmax, 2 barriers/tile ========
    float Mrun = NEG_INF;
    float den_l = 0.f;                 // per-lane distributed denominator
    float pd[16];
#pragma unroll
    for (int i = 0; i < 16; i++) pd[i] = 0.f;

    for (int t = 0; t < NTC; t++) {
        const int st = t % 3;
        if (t == NTC - 1) cp_wait0(); else cp_wait1();
        __syncthreads();   // S0: tile t ready; stage (t%3) from t-3 consumed

        if (t + 2 < NTC) {
            issue_tile(bufb + (uint32_t)((t + 2) % 3) * TILE_BYTES,
                       xb, t + 2, tid);
            cp_commit();
        }

        const float* B = buf + st * (DD * TT);
        // phase L: warp aw covers d = aw*16..+15, k = lane
        {
            float acc = 0.f;
#pragma unroll
            for (int j = 0; j < 16; j++) {
                const int d = aw * 16 + j;
                acc = fmaf(q2s[d], B[d * TT + lane], acc);
            }
            part[aw * TT + lane] = acc;
        }
        __syncthreads();   // B1

        // every warp redundantly: combine partials, mask, max, alpha, weight
        float l = 0.f;
#pragma unroll
        for (int g = 0; g < 8; g++) l += part[g * TT + lane];
        l = ((mbits >> t) & 1u) ? l : NEG_INF;
        const float tm = warp_max(l);
        const float nM = fmaxf(Mrun, tm);
        const float alpha = (nM == NEG_INF) ? 0.f : __expf(Mrun - nM);
        const float w     = (nM == NEG_INF) ? 0.f : __expf(l - nM);
        Mrun = nM;
        den_l = fmaf(den_l, alpha, w);   // lane-local; reduced once at the end

#pragma unroll
        for (int ii = 0; ii < 16; ii++) {
            const int d = aw * 16 + ii;
            pd[ii] = fmaf(pd[ii], alpha, w * B[d * TT + lane]);
        }
        // next iteration's S0 protects part + stage reuse
    }

    // ================= epilogue: partials + last-block combine =================
#pragma unroll
    for (int ii = 0; ii < 16; ii++) {
        const float s = warp_sum(pd[ii]);
        if (lane == 0) g_pp[(bn * NCH + c) * DD + aw * 16 + ii] = s;
    }
    const float den = warp_sum(den_l);   // same value in every warp
    if (tid == 0) {
        g_ps[bn * NCH + c] = den;
        g_pm[bn * NCH + c] = Mrun;
        __threadfence();
        const unsigned old = atomicAdd(&g_sync[BN + bn], 1u);
        ((unsigned*)scal)[0] = old;
    }
    __syncthreads();

    if (((const unsigned*)scal)[0] == (unsigned)(NCH - 1)) {
        __threadfence();   // acquire: partials from sibling blocks
        if (tid < DD) {
            float pm[NCH];
            float M = NEG_INF;
#pragma unroll
            for (int c2 = 0; c2 < NCH; c2++) {
                pm[c2] = g_pm[bn * NCH + c2];
                M = fmaxf(M, pm[c2]);
            }
            float num = 0.f, dsum = 0.f;
#pragma unroll
            for (int c2 = 0; c2 < NCH; c2++) {
                const float e = __expf(pm[c2] - M);   // exp(-inf - finite) = 0
                num  = fmaf(e, g_pp[(bn * NCH + c2) * DD + tid], num);
                dsum = fmaf(e, g_ps[bn * NCH + c2], dsum);
            }
            out[bn * DD + tid] = num / dsum;
        }
    }
}

extern "C" void kernel_launch(void* const* d_in, const int* in_sizes, int n_in,
                              void* d_out, int out_size) {
    const float* x    = (const float*)d_in[0];
    const int*   mask = (const int*)d_in[1];
    const float* Wq   = (const float*)d_in[2];
    const float* bq   = (const float*)d_in[3];
    const float* Wk   = (const float*)d_in[4];
    const float* bk   = (const float*)d_in[5];
    float* out = (float*)d_out;
    (void)bk; (void)in_sizes; (void)n_in; (void)out_size;  // bk cancels in softmax

    void* sp = nullptr;
    cudaGetSymbolAddress(&sp, g_sync);
    cudaMemsetAsync(sp, 0, 2 * BN * sizeof(unsigned int));

    const size_t smem = (size_t)SMF * sizeof(float);
    cudaFuncSetAttribute(fused_attn_pool,
                         cudaFuncAttributeMaxDynamicSharedMemorySize, (int)smem);
    fused_attn_pool<<<BN * NCH, NTH, smem>>>(x, mask, Wq, bq, Wk, out);
}

// round 17
// speedup vs baseline: 1.4326x; 1.0538x over previous
#include <cuda_runtime.h>
#include <math.h>
#include <stdint.h>

// AttnPooling B=8,N=16 -> BN=128; D=128; K=4096.
// l_k = q.(Wk x_k + bk) = (Wk^T q).x_k + const (cancels in softmax).
// SINGLE fused kernel, 256 blocks = 128 bn-pairs x 2 chunks, 512 threads,
// occ 2 (all resident). Per block: pass A masked-sum over its 2048-k chunk ->
// pair atomic barrier -> redundant q2 -> pass B online-softmax pooling
// (ring-2 cp.async, TT=64 -> 256B/row segments, 3-barrier clog softmax) ->
// last block of each pair combines.

#define BN  128
#define DD  128
#define KK  4096
#define NCH 2
#define CK  (KK / NCH)       // 2048 k per chunk
#define TT  64               // k-tile in pass B (256B per row segment)
#define NTC (CK / TT)        // 32 tiles
#define NTH 512
#define NW  16               // warps
#define TILE_FLOATS (DD * TT)        // 8192
#define TILE_BYTES  (TILE_FLOATS * 4)

// scratch (__device__ globals: no allocation)
__device__ float g_sum[BN * NCH * DD];
__device__ float g_cnt[BN * NCH];
__device__ float g_pp[BN * NCH * DD];
__device__ float g_pm[BN * NCH];
__device__ float g_ps[BN * NCH];
__device__ unsigned int g_sync[2 * BN];

// smem float offsets
#define OFF_BUF  0                          // 2 x 8192
#define OFF_MSK  (2 * TILE_FLOATS)          // 16384 ; mask (CK floats)
#define OFF_CLOG (OFF_MSK + CK)             // 18432 ; chunk logits (CK floats)
#define OFF_PART (OFF_CLOG + CK)            // 20480 ; 16 warps x 64 = 1024 (also mean+q)
#define OFF_Q2   (OFF_PART + NW * TT)       // 21504
#define OFF_RED  (OFF_Q2 + DD)              // 21632
#define OFF_SCAL (OFF_RED + 32)             // 21664
#define SMF      (OFF_SCAL + 4)             // 21668 floats = 86672 B -> occ 2

__device__ __forceinline__ float warp_sum(float v) {
#pragma unroll
    for (int o = 16; o > 0; o >>= 1) v += __shfl_xor_sync(0xffffffffu, v, o);
    return v;
}
__device__ __forceinline__ float warp_max(float v) {
#pragma unroll
    for (int o = 16; o > 0; o >>= 1) v = fmaxf(v, __shfl_xor_sync(0xffffffffu, v, o));
    return v;
}
__device__ __forceinline__ uint32_t smem_u32(const void* p) {
    uint32_t a;
    asm("{ .reg .u64 t; cvta.to.shared.u64 t, %1; cvt.u32.u64 %0, t; }" : "=r"(a) : "l"(p));
    return a;
}
__device__ __forceinline__ void cp_async16(uint32_t dst, const void* src) {
    asm volatile("cp.async.cg.shared.global [%0], [%1], 16;" :: "r"(dst), "l"(src) : "memory");
}
__device__ __forceinline__ void cp_commit() {
    asm volatile("cp.async.commit_group;" ::: "memory");
}
__device__ __forceinline__ void cp_wait0() {
    asm volatile("cp.async.wait_group 0;" ::: "memory");
}
__device__ __forceinline__ void cp_wait1() {
    asm volatile("cp.async.wait_group 1;" ::: "memory");
}

// one tile = 128 rows x 64 floats = 2048 float4; 512 thr x 4 copies
// row segment = 256B contiguous (activate-friendly vs 128B)
__device__ __forceinline__ void issue_tile(uint32_t base, const float* __restrict__ xb,
                                           int rt, int tid) {
#pragma unroll
    for (int j = 0; j < 4; j++) {
        const int idx = tid + NTH * j;
        const int row = idx >> 4;          // 16 float4 per row
        const int c4  = idx & 15;
        cp_async16(base + (uint32_t)row * (TT * 4) + (uint32_t)c4 * 16,
                   xb + (size_t)row * KK + rt * TT + c4 * 4);
    }
}

__global__ void __launch_bounds__(NTH, 2)
fused_attn_pool(const float* __restrict__ x, const int* __restrict__ mask,
                const float* __restrict__ Wq, const float* __restrict__ bq,
                const float* __restrict__ Wk, float* __restrict__ out)
{
    extern __shared__ float sm[];
    float* buf  = sm + OFF_BUF;
    float* msk  = sm + OFF_MSK;
    float* clog = sm + OFF_CLOG;
    float* part = sm + OFF_PART;      // logit partials; also mean(0..127)+q(128..255)
    float* q2s  = sm + OFF_Q2;
    float* reds = sm + OFF_RED;
    float* scal = sm + OFF_SCAL;

    const int tid  = threadIdx.x;
    const int lane = tid & 31;
    const int aw   = tid >> 5;        // 16 warps
    const int bn   = blockIdx.x >> 1;
    const int c    = blockIdx.x & 1;
    const float NEG_INF = __int_as_float(0xff800000);

    const float* xb = x + (size_t)bn * (DD * KK) + (size_t)c * CK;
    const int*   mb = mask + (size_t)bn * KK + (size_t)c * CK;
    const uint32_t bufb = smem_u32(buf);

    // ================= pass A: mask + masked partial sums =================
    float cnt = 0.f;
#pragma unroll
    for (int j = 0; j < CK / NTH; j++) {
        const int i = tid + j * NTH;
        const float v = (float)mb[i];
        msk[i] = v;
        cnt += v;
    }
    cnt = warp_sum(cnt);
    if (lane == 0) reds[aw] = cnt;
    __syncthreads();
    if (tid == 0) {
        float s = 0.f;
#pragma unroll
        for (int w = 0; w < NW; w++) s += reds[w];
        g_cnt[bn * NCH + c] = s;
    }

    const float4* m4 = (const float4*)msk;
    // warp aw handles rows d = aw*8 + i ; each row = 4KB contiguous read
#pragma unroll 2
    for (int i = 0; i < 8; i++) {
        const int d = aw * 8 + i;
        const float* row = xb + (size_t)d * KK;
        float s = 0.f;
#pragma unroll
        for (int j = 0; j < 16; j++) {
            const float4 v = *(const float4*)(row + j * 128 + lane * 4);
            const float4 m = m4[j * 32 + lane];
            s = fmaf(v.x, m.x, s);
            s = fmaf(v.y, m.y, s);
            s = fmaf(v.z, m.z, s);
            s = fmaf(v.w, m.w, s);
        }
        s = warp_sum(s);
        if (lane == 0) g_sum[(bn * NCH + c) * DD + d] = s;
    }
    __syncthreads();   // all g_sum/g_cnt stores issued; msk stable

    // prefetch first two pass-B tiles (overlaps pair sync + q2 compute)
    issue_tile(bufb,              xb, 0, tid); cp_commit();
    issue_tile(bufb + TILE_BYTES, xb, 1, tid); cp_commit();

    // ============== pair barrier (2 chunk-blocks of this bn) ==============
    if (tid == 0) {
        __threadfence();
        atomicAdd(&g_sync[bn], 1u);
        while (((volatile unsigned int*)g_sync)[bn] < (unsigned)NCH) __nanosleep(64);
        __threadfence();
    }
    __syncthreads();

    // ============== redundant q2 compute (per block) ==============
    float* mean_s = part;            // [0..127]
    float* q_s    = part + 128;      // [128..255]
    if (tid < DD) {
        float cs = 0.f, ss = 0.f;
#pragma unroll
        for (int c2 = 0; c2 < NCH; c2++) {
            cs += g_cnt[bn * NCH + c2];
            ss += g_sum[(bn * NCH + c2) * DD + tid];
        }
        mean_s[tid] = ss / cs;
    }
    __syncthreads();
#pragma unroll 2
    for (int ii = 0; ii < 8; ii++) {
        const int r = aw * 8 + ii;
        float s = 0.f;
#pragma unroll
        for (int b = 0; b < 4; b++) {
            const int j = lane + 32 * b;
            s = fmaf(Wq[r * DD + j], mean_s[j], s);
        }
        s = warp_sum(s);
        if (lane == 0) q_s[r] = s + bq[r];
    }
    __syncthreads();
    float q2v = 0.f;
    if (tid < DD) {
#pragma unroll 8
        for (int j = 0; j < DD; j++)
            q2v = fmaf(Wk[j * DD + tid], q_s[j], q2v);
    }
    __syncthreads();   // mean/q dead (part reused next)
    if (tid < DD) q2s[tid] = q2v * 0.08838834764831845f;   // 1/sqrt(128)
    __syncthreads();   // q2s visible

    // ======== pass B: online softmax, ring-2, 3-barrier clog form ========
    float Mrun = NEG_INF;
    float pd[8];
#pragma unroll
    for (int i = 0; i < 8; i++) pd[i] = 0.f;

    for (int t = 0; t < NTC; t++) {
        const int st = t & 1;
        if (t == 0) cp_wait1(); else cp_wait0();
        __syncthreads();   // S0: tile t visible to all; stage st^1 (tile t-1) consumed

        // issue tile t+1 into the stage just freed (t>=1; t=0,1 pre-issued)
        if (t >= 1 && t + 1 < NTC) {
            issue_tile(bufb + (uint32_t)((t + 1) & 1) * TILE_BYTES, xb, t + 1, tid);
            cp_commit();
        }

        const float* B = buf + st * TILE_FLOATS;
        // phase L: warp aw covers d = aw*8..+7 ; lane owns k = lane, lane+32
        {
            float a0 = 0.f, a1 = 0.f;
#pragma unroll
            for (int j = 0; j < 8; j++) {
                const int d = aw * 8 + j;
                const float qd = q2s[d];
                a0 = fmaf(qd, B[d * TT + lane], a0);
                a1 = fmaf(qd, B[d * TT + 32 + lane], a1);
            }
            part[aw * TT + lane]      = a0;
            part[aw * TT + 32 + lane] = a1;
        }
        __syncthreads();   // B1

        if (tid < TT) {
            float l = 0.f;
#pragma unroll
            for (int g = 0; g < NW; g++) l += part[g * TT + tid];
            if (msk[t * TT + tid] == 0.f) l = NEG_INF;
            clog[t * TT + tid] = l;
        }
        __syncthreads();   // B2

        // every warp: tile max, alpha, weights (reads same 64 logits)
        const float l0 = clog[t * TT + lane];
        const float l1 = clog[t * TT + 32 + lane];
        const float tm = warp_max(fmaxf(l0, l1));
        const float nM = fmaxf(Mrun, tm);
        const float alpha = (nM == NEG_INF) ? 0.f : __expf(Mrun - nM);
        const float w0    = (nM == NEG_INF) ? 0.f : __expf(l0 - nM);
        const float w1    = (nM == NEG_INF) ? 0.f : __expf(l1 - nM);
        Mrun = nM;

#pragma unroll
        for (int ii = 0; ii < 8; ii++) {
            const int d = aw * 8 + ii;
            float rs = w0 * B[d * TT + lane];
            rs = fmaf(w1, B[d * TT + 32 + lane], rs);
            pd[ii] = fmaf(pd[ii], alpha, rs);
        }
        // next iteration's S0 protects part + stage reuse
    }

    // ================= epilogue: partials + last-block combine =================
#pragma unroll
    for (int ii = 0; ii < 8; ii++) {
        const float s = warp_sum(pd[ii]);
        if (lane == 0) g_pp[(bn * NCH + c) * DD + aw * 8 + ii] = s;
    }
    // denominator from cached chunk logits with final max
    const float Mf = Mrun;
    float ds = 0.f;
#pragma unroll
    for (int j = 0; j < CK / NTH; j++) {
        const float l = clog[tid + NTH * j];
        ds += (Mf == NEG_INF) ? 0.f : __expf(l - Mf);
    }
    ds = warp_sum(ds);
    if (lane == 0) reds[aw] = ds;
    __syncthreads();
    if (tid == 0) {
        float s = 0.f;
#pragma unroll
        for (int w = 0; w < NW; w++) s += reds[w];
        g_ps[bn * NCH + c] = s;
        g_pm[bn * NCH + c] = Mf;
        __threadfence();
        const unsigned old = atomicAdd(&g_sync[BN + bn], 1u);
        ((unsigned*)scal)[0] = old;
    }
    __syncthreads();

    if (((const unsigned*)scal)[0] == (unsigned)(NCH - 1)) {
        __threadfence();   // acquire: partials from sibling block
        if (tid < DD) {
            float pm[NCH];
            float M = NEG_INF;
#pragma unroll
            for (int c2 = 0; c2 < NCH; c2++) {
                pm[c2] = g_pm[bn * NCH + c2];
                M = fmaxf(M, pm[c2]);
            }
            float num = 0.f, dsum = 0.f;
#pragma unroll
            for (int c2 = 0; c2 < NCH; c2++) {
                const float e = __expf(pm[c2] - M);   // exp(-inf - finite) = 0
                num  = fmaf(e, g_pp[(bn * NCH + c2) * DD + tid], num);
                dsum = fmaf(e, g_ps[bn * NCH + c2], dsum);
            }
            out[bn * DD + tid] = num / dsum;
        }
    }
}

extern "C" void kernel_launch(void* const* d_in, const int* in_sizes, int n_in,
                              void* d_out, int out_size) {
    const float* x    = (const float*)d_in[0];
    const int*   mask = (const int*)d_in[1];
    const float* Wq   = (const float*)d_in[2];
    const float* bq   = (const float*)d_in[3];
    const float* Wk   = (const float*)d_in[4];
    const float* bk   = (const float*)d_in[5];
    float* out = (float*)d_out;
    (void)bk; (void)in_sizes; (void)n_in; (void)out_size;  // bk cancels in softmax

    void* sp = nullptr;
    cudaGetSymbolAddress(&sp, g_sync);
    cudaMemsetAsync(sp, 0, 2 * BN * sizeof(unsigned int));

    const size_t smem = (size_t)SMF * sizeof(float);
    cudaFuncSetAttribute(fused_attn_pool,
                         cudaFuncAttributeMaxDynamicSharedMemorySize, (int)smem);
    fused_attn_pool<<<BN * NCH, NTH, smem>>>(x, mask, Wq, bq, Wk, out);
}